// round 2
// baseline (speedup 1.0000x reference)
#include <cuda_runtime.h>

#define E_EDGES 250000
#define TILE_E  128
#define NBLOCKS ((E_EDGES + TILE_E - 1) / TILE_E)

using u64 = unsigned long long;

__device__ __forceinline__ u64 ffma2(u64 a, u64 b, u64 c) {
    u64 d;
    asm("fma.rn.f32x2 %0, %1, %2, %3;" : "=l"(d) : "l"(a), "l"(b), "l"(c));
    return d;
}
__device__ __forceinline__ u64 dup2(float x) {
    u64 d;
    asm("mov.b64 %0, {%1, %1};" : "=l"(d) : "f"(x));
    return d;
}
__device__ __forceinline__ float lo32(u64 v) { return __uint_as_float((unsigned)(v & 0xffffffffu)); }
__device__ __forceinline__ float hi32(u64 v) { return __uint_as_float((unsigned)(v >> 32)); }

// Shared layout (bytes):
//   w01s : float2[64*64]  [0, 32768)
//   w2s  : float [64*64]  [32768, 49152)
//   invp : float2[64*65]  [49152, 82432)   row pad 65 kills STS bank conflicts
//   shs  : float [128*9]  [82432, 87040)
#define SMEM_BYTES 87040

__global__ __launch_bounds__(256)
void sh_tensor_embed_kernel(const float* __restrict__ vec,
                            const float* __restrict__ inv,
                            const float* __restrict__ W,
                            float* __restrict__ out) {
    extern __shared__ char sm[];
    float2* w01s = (float2*)(sm);
    float*  w2s  = (float*) (sm + 32768);
    float2* invp = (float2*)(sm + 49152);
    float*  shs  = (float*) (sm + 82432);

    const int tid = threadIdx.x;
    const int e0  = blockIdx.x * TILE_E;

    // ---- fill W tiles (channel-swizzled so mainloop LDS is conflict-free) ----
    for (int idx = tid; idx < 64 * 64; idx += 256) {
        int d = idx >> 6, c = idx & 63;
        int s = (c >> 2) | ((c & 3) << 4);
        const float* g = W + d * 192 + c * 3;
        w01s[d * 64 + s] = make_float2(g[0], g[1]);
        w2s [d * 64 + s] = g[2];
    }
    // ---- fill edge-invariant tile, pair-interleaved for f32x2 ----
    for (int idx = tid; idx < TILE_E * 64; idx += 256) {
        int el = idx >> 6, d = idx & 63;
        int e = e0 + el; if (e >= E_EDGES) e = E_EDGES - 1;
        float v = inv[(size_t)e * 64 + d];
        ((float*)invp)[(d * 65 + (el >> 1)) * 2 + (el & 1)] = v;
    }
    // ---- spherical harmonics per edge ----
    if (tid < TILE_E) {
        int e = e0 + tid; if (e >= E_EDGES) e = E_EDGES - 1;
        float x = vec[(size_t)e * 3 + 0];
        float y = vec[(size_t)e * 3 + 1];
        float z = vec[(size_t)e * 3 + 2];
        float r = rsqrtf(x * x + y * y + z * z);
        x *= r; y *= r; z *= r;
        const float s3  = 1.7320508075688772f;   // sqrt(3)
        const float s5  = 2.2360679774997896f;   // sqrt(5)
        const float s15 = 3.8729833462074170f;   // sqrt(15)
        float* o = shs + tid * 9;
        o[0] = 1.0f;
        o[1] = s3 * x;
        o[2] = s3 * y;
        o[3] = s3 * z;
        o[4] = s15 * x * z;
        o[5] = s15 * x * y;
        o[6] = s5 * (y * y - 0.5f * (x * x + z * z));
        o[7] = s15 * y * z;
        o[8] = 0.5f * s15 * (z * z - x * x);
    }
    __syncthreads();

    // thread tile: 4 contiguous channels (c0 = cg*4), 8 edges (4 pairs)
    const int cg = tid & 15;
    const int eg = tid >> 4;

    u64 acc[4][4][3];
    #pragma unroll
    for (int i = 0; i < 4; i++)
        #pragma unroll
        for (int j = 0; j < 4; j++)
            #pragma unroll
            for (int r = 0; r < 3; r++)
                acc[i][j][r] = 0ull;

    const float2* wp  = w01s + cg;            // channel i lives at slot cg + 16*i
    const float*  w2p = w2s  + cg;
    const float2* ip  = invp + eg * 4;        // 4 pairs for this thread

    #pragma unroll 8
    for (int d = 0; d < 64; d++) {
        u64 pv[4];
        #pragma unroll
        for (int j = 0; j < 4; j++)
            pv[j] = *(const u64*)&ip[d * 65 + j];          // {inv[2p], inv[2p+1]}
        #pragma unroll
        for (int i = 0; i < 4; i++) {
            float2 w01 = wp [d * 64 + i * 16];
            float  w2v = w2p[d * 64 + i * 16];
            u64 W0 = dup2(w01.x), W1 = dup2(w01.y), W2 = dup2(w2v);
            #pragma unroll
            for (int j = 0; j < 4; j++) {
                acc[i][j][0] = ffma2(pv[j], W0, acc[i][j][0]);
                acc[i][j][1] = ffma2(pv[j], W1, acc[i][j][1]);
                acc[i][j][2] = ffma2(pv[j], W2, acc[i][j][2]);
            }
        }
    }

    // ---- epilogue: out[e][c][i] = sh[i] * w[c][widx[i]], 9 aligned float4 per edge ----
    #pragma unroll
    for (int j = 0; j < 4; j++) {
        #pragma unroll
        for (int h = 0; h < 2; h++) {
            int el = eg * 8 + j * 2 + h;
            int e = e0 + el;
            if (e < E_EDGES) {
                const float* shp = shs + el * 9;
                float shv[9];
                #pragma unroll
                for (int k = 0; k < 9; k++) shv[k] = shp[k];
                float w[4][3];
                #pragma unroll
                for (int i = 0; i < 4; i++)
                    #pragma unroll
                    for (int r = 0; r < 3; r++)
                        w[i][r] = h ? hi32(acc[i][j][r]) : lo32(acc[i][j][r]);

                float vals[36];
                #pragma unroll
                for (int i = 0; i < 4; i++)
                    #pragma unroll
                    for (int k = 0; k < 9; k++) {
                        int r = (k == 0) ? 0 : ((k < 4) ? 1 : 2);
                        vals[i * 9 + k] = shv[k] * w[i][r];
                    }
                float4* p = (float4*)(out + (size_t)e * 576 + cg * 36);
                #pragma unroll
                for (int q = 0; q < 9; q++)
                    p[q] = make_float4(vals[4 * q], vals[4 * q + 1],
                                       vals[4 * q + 2], vals[4 * q + 3]);
            }
        }
    }
}

extern "C" void kernel_launch(void* const* d_in, const int* in_sizes, int n_in,
                              void* d_out, int out_size) {
    const float* vec = nullptr;
    const float* inv = nullptr;
    const float* W   = nullptr;
    for (int i = 0; i < n_in; i++) {
        if      (in_sizes[i] == E_EDGES * 3)  vec = (const float*)d_in[i];
        else if (in_sizes[i] == E_EDGES * 64) inv = (const float*)d_in[i];
        else if (in_sizes[i] == 64 * 192)     W   = (const float*)d_in[i];
    }
    cudaFuncSetAttribute(sh_tensor_embed_kernel,
                         cudaFuncAttributeMaxDynamicSharedMemorySize, SMEM_BYTES);
    sh_tensor_embed_kernel<<<NBLOCKS, 256, SMEM_BYTES>>>(vec, inv, W, (float*)d_out);
}